// round 2
// baseline (speedup 1.0000x reference)
#include <cuda_runtime.h>
#include <cuda_bf16.h>
#include <cstdint>

// ---------------- problem constants ----------------
static constexpr int BATCH    = 1024;
static constexpr int HIST     = 50;
static constexpr int N_ITEMS  = 100000;
static constexpr int IN_CH    = 64;

static constexpr int N_TILE   = 128;              // N per CTA
static constexpr int NPAD     = 100096;           // 782 * 128
static constexpr int N_CTAS   = NPAD / N_TILE;    // 782
static constexpr int M_TILE   = 128;
static constexpr int M_CHUNKS = BATCH / M_TILE;   // 8
static constexpr int SEGS     = 3;                // AhBh + AhBl + AlBh
static constexpr int KSEG     = 64;               // bf16 per seg (=128B row)
static constexpr int KROW     = SEGS * KSEG;      // 192 bf16 per logical row

static constexpr int SEG_B    = 128 * 128;        // bytes per seg tile (128 rows x 128B)
static constexpr int TILE_B   = SEGS * SEG_B;     // 49152
static constexpr int SMEM_A   = 0;
static constexpr int SMEM_B   = TILE_B;           // 49152
static constexpr int SMEM_STG = 2 * TILE_B;       // 98304
static constexpr int STG_STRIDE = 33;             // floats
static constexpr int SMEM_TOTAL = SMEM_STG + M_TILE * STG_STRIDE * 4; // 115200

// scratch (device globals; allocation-free rule). g_B pad rows stay zero.
__device__ __align__(16) __nv_bfloat16 g_A[BATCH * KROW];
__device__ __align__(16) __nv_bfloat16 g_B[NPAD * KROW];

// ---------------- helpers ----------------
__device__ __forceinline__ uint32_t smem_u32(const void* p) {
    uint32_t a;
    asm("{ .reg .u64 t; cvta.to.shared.u64 t, %1; cvt.u32.u64 %0, t; }" : "=r"(a) : "l"(p));
    return a;
}
#define SWZ128(o) ((o) ^ (((o) >> 3) & 0x70))

__device__ __forceinline__ void ldsm_x4(uint32_t addr, uint32_t& r0, uint32_t& r1,
                                        uint32_t& r2, uint32_t& r3) {
    asm volatile("ldmatrix.sync.aligned.m8n8.x4.shared.b16 {%0,%1,%2,%3}, [%4];"
                 : "=r"(r0), "=r"(r1), "=r"(r2), "=r"(r3) : "r"(addr));
}
__device__ __forceinline__ void mma16816(float* c, const uint32_t* a, uint32_t b0, uint32_t b1) {
    asm volatile(
        "mma.sync.aligned.m16n8k16.row.col.f32.bf16.bf16.f32 "
        "{%0,%1,%2,%3}, {%4,%5,%6,%7}, {%8,%9}, {%0,%1,%2,%3};"
        : "+f"(c[0]), "+f"(c[1]), "+f"(c[2]), "+f"(c[3])
        : "r"(a[0]), "r"(a[1]), "r"(a[2]), "r"(a[3]), "r"(b0), "r"(b1));
}

// ---------------- prep kernels ----------------
__device__ __forceinline__ void split1(float x, __nv_bfloat16& h, __nv_bfloat16& l) {
    h = __float2bfloat16_rn(x);
    l = __float2bfloat16_rn(x - __bfloat162float(h));
}

__global__ void k_init(float* out) { if (threadIdx.x == 0) out[0] = 0.0f; }

__global__ void k_prepA(const float* __restrict__ user_emb, const int* __restrict__ uid) {
    int gid = blockIdx.x * blockDim.x + threadIdx.x;   // BATCH*16
    int b = gid >> 4, q = gid & 15;
    int u = uid[b];
    float4 v = reinterpret_cast<const float4*>(user_emb)[(size_t)u * 16 + q];
    union { __nv_bfloat16 h[4]; uint2 u2; } H, L;
    split1(v.x, H.h[0], L.h[0]); split1(v.y, H.h[1], L.h[1]);
    split1(v.z, H.h[2], L.h[2]); split1(v.w, H.h[3], L.h[3]);
    __nv_bfloat16* row = g_A + (size_t)b * KROW + q * 4;
    *reinterpret_cast<uint2*>(row)       = H.u2;   // seg0: Ah
    *reinterpret_cast<uint2*>(row + 64)  = H.u2;   // seg1: Ah
    *reinterpret_cast<uint2*>(row + 128) = L.u2;   // seg2: Al
}

__global__ void k_prepB(const float* __restrict__ item_emb) {
    int gid = blockIdx.x * blockDim.x + threadIdx.x;   // NPAD*16
    int r = gid >> 4, q = gid & 15;
    if (r >= N_ITEMS) return;
    float4 v = reinterpret_cast<const float4*>(item_emb)[(size_t)r * 16 + q];
    union { __nv_bfloat16 h[4]; uint2 u2; } H, L;
    split1(v.x, H.h[0], L.h[0]); split1(v.y, H.h[1], L.h[1]);
    split1(v.z, H.h[2], L.h[2]); split1(v.w, H.h[3], L.h[3]);
    __nv_bfloat16* row = g_B + (size_t)r * KROW + q * 4;
    *reinterpret_cast<uint2*>(row)       = H.u2;   // seg0: Bh
    *reinterpret_cast<uint2*>(row + 64)  = L.u2;   // seg1: Bl
    *reinterpret_cast<uint2*>(row + 128) = H.u2;   // seg2: Bh
}

// ---------------- main GEMM + squares ----------------
// CTA: 256 thr = 8 warps, warp grid 2(M) x 4(N), warp tile 64x32.
__global__ __launch_bounds__(256, 1) void k_gemm(float* __restrict__ out) {
    extern __shared__ char smem[];
    const uint32_t sb   = smem_u32(smem);
    const uint32_t sA   = sb + SMEM_A;
    const uint32_t sB   = sb + SMEM_B;
    float* stage = reinterpret_cast<float*>(smem + SMEM_STG);

    const int tid  = threadIdx.x, wid = tid >> 5, lane = tid & 31;
    const int wm   = wid & 1, wn = wid >> 1;
    const int n0   = blockIdx.x * N_TILE;

    // --- load B tile [128 rows, 3 segs x 128B] with SW128 swizzle (persists) ---
    for (int i = tid; i < 128 * 24; i += 256) {
        int row = i / 24, r = i % 24, seg = r >> 3, c16 = r & 7;
        uint4 v = *reinterpret_cast<const uint4*>(
            g_B + (size_t)(n0 + row) * KROW + seg * KSEG + c16 * 8);
        *reinterpret_cast<uint4*>(smem + SMEM_B + seg * SEG_B +
                                  row * 128 + ((c16 * 16) ^ ((row & 7) * 16))) = v;
    }

    // per-lane ldmatrix row bases (row -> byte offset + swizzle xor)
    const int la15 = lane & 15, half = lane >> 4;
    float sq = 0.0f;

    for (int mc = 0; mc < M_CHUNKS; mc++) {
        const int m0 = mc * M_TILE;
        // --- load A tile ---
        for (int i = tid; i < 128 * 24; i += 256) {
            int row = i / 24, r = i % 24, seg = r >> 3, c16 = r & 7;
            uint4 v = *reinterpret_cast<const uint4*>(
                g_A + (size_t)(m0 + row) * KROW + seg * KSEG + c16 * 8);
            *reinterpret_cast<uint4*>(smem + SMEM_A + seg * SEG_B +
                                      row * 128 + ((c16 * 16) ^ ((row & 7) * 16))) = v;
        }
        __syncthreads();

        float acc[4][4][4];   // [mt][nt8][4]
        #pragma unroll
        for (int i = 0; i < 4; i++)
            #pragma unroll
            for (int j = 0; j < 4; j++)
                #pragma unroll
                for (int k = 0; k < 4; k++) acc[i][j][k] = 0.0f;

        #pragma unroll
        for (int seg = 0; seg < SEGS; seg++) {
            const uint32_t aSeg = sA + seg * SEG_B;
            const uint32_t bSeg = sB + seg * SEG_B;
            #pragma unroll
            for (int ks = 0; ks < 4; ks++) {        // 4 x k16 = K64 per seg
                const uint32_t koff = ks * 32 + half * 16;
                uint32_t a[4][4], b[2][4];
                #pragma unroll
                for (int mt = 0; mt < 4; mt++) {
                    int row = wm * 64 + mt * 16 + la15;
                    ldsm_x4(aSeg + row * 128 + (koff ^ ((row & 7) * 16)),
                            a[mt][0], a[mt][1], a[mt][2], a[mt][3]);
                }
                #pragma unroll
                for (int g = 0; g < 2; g++) {
                    int row = wn * 32 + g * 16 + la15;
                    ldsm_x4(bSeg + row * 128 + (koff ^ ((row & 7) * 16)),
                            b[g][0], b[g][1], b[g][2], b[g][3]);
                }
                #pragma unroll
                for (int mt = 0; mt < 4; mt++)
                    #pragma unroll
                    for (int g = 0; g < 2; g++) {
                        mma16816(acc[mt][2 * g],     a[mt], b[g][0], b[g][2]);
                        mma16816(acc[mt][2 * g + 1], a[mt], b[g][1], b[g][3]);
                    }
            }
        }
        __syncthreads();   // mma reads done before A tile reuse / stage reuse

        // --- epilogue: 4 slabs of 32 cols; stage -> coalesced store + squares ---
        for (int slab = 0; slab < 4; slab++) {
            if (wn == slab) {
                #pragma unroll
                for (int mt = 0; mt < 4; mt++) {
                    int r0 = wm * 64 + mt * 16 + (lane >> 2);
                    #pragma unroll
                    for (int nt = 0; nt < 4; nt++) {
                        int c0 = nt * 8 + 2 * (lane & 3);
                        float v0 = acc[mt][nt][0], v1 = acc[mt][nt][1];
                        float v2 = acc[mt][nt][2], v3 = acc[mt][nt][3];
                        sq += v0 * v0 + v1 * v1 + v2 * v2 + v3 * v3;
                        stage[r0 * STG_STRIDE + c0]           = v0;
                        stage[r0 * STG_STRIDE + c0 + 1]       = v1;
                        stage[(r0 + 8) * STG_STRIDE + c0]     = v2;
                        stage[(r0 + 8) * STG_STRIDE + c0 + 1] = v3;
                    }
                }
            }
            __syncthreads();
            const int colg = n0 + slab * 32 + lane;
            if (colg < N_ITEMS) {
                float* op = out + 1 + (size_t)(m0 + wid * 16) * N_ITEMS + colg;
                #pragma unroll
                for (int r = 0; r < 16; r++)
                    op[(size_t)r * N_ITEMS] = stage[(wid * 16 + r) * STG_STRIDE + lane];
            }
            __syncthreads();
        }
    }

    // reduce squares into loss (pad cols contribute exactly 0)
    #pragma unroll
    for (int o = 16; o > 0; o >>= 1) sq += __shfl_xor_sync(0xFFFFFFFFu, sq, o);
    if (lane == 0) atomicAdd(out, sq);
}

// ---------------- positives: + (1 - 2*s) per unique (row, item) ----------------
__global__ void k_pos(const float* __restrict__ user_emb, const float* __restrict__ item_emb,
                      const int* __restrict__ uid, const int* __restrict__ seq,
                      float* __restrict__ out) {
    const int b = blockIdx.x, t = threadIdx.x;   // 64 threads
    __shared__ int   s_seq[HIST];
    __shared__ float s_red[2];
    if (t < HIST) s_seq[t] = seq[b * HIST + t];
    const float su = user_emb[(size_t)uid[b] * IN_CH + t];
    __syncthreads();
    float contrib = 0.0f;
    for (int j = 0; j < HIST; j++) {
        int idx = s_seq[j];
        bool dup = false;
        for (int jj = 0; jj < j; jj++) dup |= (s_seq[jj] == idx);
        if (!dup) {
            float p = su * item_emb[(size_t)idx * IN_CH + t];
            #pragma unroll
            for (int o = 16; o > 0; o >>= 1) p += __shfl_xor_sync(0xFFFFFFFFu, p, o);
            if ((t & 31) == 0) s_red[t >> 5] = p;
            __syncthreads();
            if (t == 0) contrib += 1.0f - 2.0f * (s_red[0] + s_red[1]);
            __syncthreads();
        }
    }
    if (t == 0) atomicAdd(out, contrib);
}

// ---------------- launch ----------------
extern "C" void kernel_launch(void* const* d_in, const int* in_sizes, int n_in,
                              void* d_out, int out_size) {
    const float* user_emb = (const float*)d_in[0];
    const float* item_emb = (const float*)d_in[1];
    const int*   uid      = (const int*)d_in[2];
    const int*   seq      = (const int*)d_in[3];
    float*       out      = (float*)d_out;   // [0]=loss, [1..]=pref row-major

    cudaFuncSetAttribute(k_gemm, cudaFuncAttributeMaxDynamicSharedMemorySize, SMEM_TOTAL);

    k_init<<<1, 32>>>(out);
    k_prepA<<<(BATCH * 16) / 256, 256>>>(user_emb, uid);
    k_prepB<<<(NPAD * 16) / 256, 256>>>(item_emb);
    k_gemm<<<N_CTAS, 256, SMEM_TOTAL>>>(out);
    k_pos<<<BATCH, 64>>>(user_emb, item_emb, uid, seq, out);
}

// round 3
// speedup vs baseline: 1.0364x; 1.0364x over previous
#include <cuda_runtime.h>
#include <cuda_bf16.h>
#include <cstdint>

// ---------------- problem constants ----------------
static constexpr int BATCH    = 1024;
static constexpr int HIST     = 50;
static constexpr int N_ITEMS  = 100000;
static constexpr int IN_CH    = 64;

static constexpr int N_TILE   = 128;              // N per CTA
static constexpr int NPAD     = 100096;           // 782 * 128
static constexpr int N_CTAS   = NPAD / N_TILE;    // 782
static constexpr int M_TILE   = 128;
static constexpr int M_CHUNKS = BATCH / M_TILE;   // 8
static constexpr int SEGS     = 3;                // AhBh + AhBl + AlBh
static constexpr int KSEG     = 64;               // bf16 per seg (=128B row)
static constexpr int KROW     = SEGS * KSEG;      // 192 bf16 per logical row

static constexpr int SEG_B    = 128 * 128;        // bytes per seg tile (128 rows x 128B)
static constexpr int TILE_B   = SEGS * SEG_B;     // 49152
static constexpr int SMEM_A   = 0;                // A tile; stage overlays this after mma
static constexpr int SMEM_B   = TILE_B;           // 49152
static constexpr int SMEM_TOTAL = 2 * TILE_B;     // 98304 -> 2 CTAs/SM
static constexpr int STG_STRIDE = 65;             // floats (64-col pair + pad)

// scratch (device globals; allocation-free rule). g_B pad rows stay zero.
__device__ __align__(16) __nv_bfloat16 g_A[BATCH * KROW];
__device__ __align__(16) __nv_bfloat16 g_B[NPAD * KROW];

// ---------------- helpers ----------------
__device__ __forceinline__ uint32_t smem_u32(const void* p) {
    uint32_t a;
    asm("{ .reg .u64 t; cvta.to.shared.u64 t, %1; cvt.u32.u64 %0, t; }" : "=r"(a) : "l"(p));
    return a;
}

__device__ __forceinline__ void ldsm_x4(uint32_t addr, uint32_t& r0, uint32_t& r1,
                                        uint32_t& r2, uint32_t& r3) {
    asm volatile("ldmatrix.sync.aligned.m8n8.x4.shared.b16 {%0,%1,%2,%3}, [%4];"
                 : "=r"(r0), "=r"(r1), "=r"(r2), "=r"(r3) : "r"(addr));
}
__device__ __forceinline__ void mma16816(float* c, const uint32_t* a, uint32_t b0, uint32_t b1) {
    asm volatile(
        "mma.sync.aligned.m16n8k16.row.col.f32.bf16.bf16.f32 "
        "{%0,%1,%2,%3}, {%4,%5,%6,%7}, {%8,%9}, {%0,%1,%2,%3};"
        : "+f"(c[0]), "+f"(c[1]), "+f"(c[2]), "+f"(c[3])
        : "r"(a[0]), "r"(a[1]), "r"(a[2]), "r"(a[3]), "r"(b0), "r"(b1));
}

// ---------------- prep kernels ----------------
__device__ __forceinline__ void split1(float x, __nv_bfloat16& h, __nv_bfloat16& l) {
    h = __float2bfloat16_rn(x);
    l = __float2bfloat16_rn(x - __bfloat162float(h));
}

__global__ void k_init(float* out) { if (threadIdx.x == 0) out[0] = 0.0f; }

__global__ void k_prepA(const float* __restrict__ user_emb, const int* __restrict__ uid) {
    int gid = blockIdx.x * blockDim.x + threadIdx.x;   // BATCH*16
    int b = gid >> 4, q = gid & 15;
    int u = uid[b];
    float4 v = reinterpret_cast<const float4*>(user_emb)[(size_t)u * 16 + q];
    union { __nv_bfloat16 h[4]; uint2 u2; } H, L;
    split1(v.x, H.h[0], L.h[0]); split1(v.y, H.h[1], L.h[1]);
    split1(v.z, H.h[2], L.h[2]); split1(v.w, H.h[3], L.h[3]);
    __nv_bfloat16* row = g_A + (size_t)b * KROW + q * 4;
    *reinterpret_cast<uint2*>(row)       = H.u2;   // seg0: Ah
    *reinterpret_cast<uint2*>(row + 64)  = H.u2;   // seg1: Ah
    *reinterpret_cast<uint2*>(row + 128) = L.u2;   // seg2: Al
}

__global__ void k_prepB(const float* __restrict__ item_emb) {
    int gid = blockIdx.x * blockDim.x + threadIdx.x;   // NPAD*16
    int r = gid >> 4, q = gid & 15;
    if (r >= N_ITEMS) return;
    float4 v = reinterpret_cast<const float4*>(item_emb)[(size_t)r * 16 + q];
    union { __nv_bfloat16 h[4]; uint2 u2; } H, L;
    split1(v.x, H.h[0], L.h[0]); split1(v.y, H.h[1], L.h[1]);
    split1(v.z, H.h[2], L.h[2]); split1(v.w, H.h[3], L.h[3]);
    __nv_bfloat16* row = g_B + (size_t)r * KROW + q * 4;
    *reinterpret_cast<uint2*>(row)       = H.u2;   // seg0: Bh
    *reinterpret_cast<uint2*>(row + 64)  = L.u2;   // seg1: Bl
    *reinterpret_cast<uint2*>(row + 128) = H.u2;   // seg2: Bh
}

// ---------------- main GEMM + squares ----------------
// CTA: 256 thr = 8 warps, warp grid 2(M) x 4(N), warp tile 64x32. 2 CTAs/SM.
__global__ __launch_bounds__(256, 2) void k_gemm(float* __restrict__ out) {
    extern __shared__ char smem[];
    const uint32_t sb   = smem_u32(smem);
    const uint32_t sA   = sb + SMEM_A;
    const uint32_t sB   = sb + SMEM_B;
    float* stage = reinterpret_cast<float*>(smem + SMEM_A);   // overlays A tile

    const int tid  = threadIdx.x, wid = tid >> 5, lane = tid & 31;
    const int wm   = wid & 1, wn = wid >> 1;
    const int n0   = blockIdx.x * N_TILE;

    // --- load B tile [128 rows, 3 segs x 128B] with SW128 swizzle (persists) ---
    for (int i = tid; i < 128 * 24; i += 256) {
        int row = i / 24, r = i % 24, seg = r >> 3, c16 = r & 7;
        uint4 v = *reinterpret_cast<const uint4*>(
            g_B + (size_t)(n0 + row) * KROW + seg * KSEG + c16 * 8);
        *reinterpret_cast<uint4*>(smem + SMEM_B + seg * SEG_B +
                                  row * 128 + ((c16 * 16) ^ ((row & 7) * 16))) = v;
    }

    const int la15 = lane & 15, half = lane >> 4;
    float sq = 0.0f;

    for (int mc = 0; mc < M_CHUNKS; mc++) {
        const int m0 = mc * M_TILE;
        __syncthreads();   // stage stores of previous chunk done before A overwrite
        // --- load A tile ---
        for (int i = tid; i < 128 * 24; i += 256) {
            int row = i / 24, r = i % 24, seg = r >> 3, c16 = r & 7;
            uint4 v = *reinterpret_cast<const uint4*>(
                g_A + (size_t)(m0 + row) * KROW + seg * KSEG + c16 * 8);
            *reinterpret_cast<uint4*>(smem + SMEM_A + seg * SEG_B +
                                      row * 128 + ((c16 * 16) ^ ((row & 7) * 16))) = v;
        }
        __syncthreads();

        float acc[4][4][4];   // [mt][nt8][4]
        #pragma unroll
        for (int i = 0; i < 4; i++)
            #pragma unroll
            for (int j = 0; j < 4; j++)
                #pragma unroll
                for (int k = 0; k < 4; k++) acc[i][j][k] = 0.0f;

        #pragma unroll
        for (int seg = 0; seg < SEGS; seg++) {
            const uint32_t aSeg = sA + seg * SEG_B;
            const uint32_t bSeg = sB + seg * SEG_B;
            #pragma unroll
            for (int ks = 0; ks < 4; ks++) {        // 4 x k16 = K64 per seg
                const uint32_t koff = ks * 32 + half * 16;
                uint32_t a[4][4], b[2][4];
                #pragma unroll
                for (int mt = 0; mt < 4; mt++) {
                    int row = wm * 64 + mt * 16 + la15;
                    ldsm_x4(aSeg + row * 128 + (koff ^ ((row & 7) * 16)),
                            a[mt][0], a[mt][1], a[mt][2], a[mt][3]);
                }
                #pragma unroll
                for (int g = 0; g < 2; g++) {
                    int row = wn * 32 + g * 16 + la15;
                    ldsm_x4(bSeg + row * 128 + (koff ^ ((row & 7) * 16)),
                            b[g][0], b[g][1], b[g][2], b[g][3]);
                }
                #pragma unroll
                for (int mt = 0; mt < 4; mt++)
                    #pragma unroll
                    for (int g = 0; g < 2; g++) {
                        mma16816(acc[mt][2 * g],     a[mt], b[g][0], b[g][2]);
                        mma16816(acc[mt][2 * g + 1], a[mt], b[g][1], b[g][3]);
                    }
            }
        }
        __syncthreads();   // mma reads of A done before stage overlays it

        // --- epilogue: 2 pairs of 64 cols; 4 warps stage, 8 warps store ---
        #pragma unroll
        for (int pair = 0; pair < 2; pair++) {
            if ((wn >> 1) == pair) {
                const int cbase = (wn & 1) * 32;
                #pragma unroll
                for (int mt = 0; mt < 4; mt++) {
                    int r0 = wm * 64 + mt * 16 + (lane >> 2);
                    #pragma unroll
                    for (int nt = 0; nt < 4; nt++) {
                        int c0 = cbase + nt * 8 + 2 * (lane & 3);
                        float v0 = acc[mt][nt][0], v1 = acc[mt][nt][1];
                        float v2 = acc[mt][nt][2], v3 = acc[mt][nt][3];
                        sq += v0 * v0 + v1 * v1 + v2 * v2 + v3 * v3;
                        stage[r0 * STG_STRIDE + c0]           = v0;
                        stage[r0 * STG_STRIDE + c0 + 1]       = v1;
                        stage[(r0 + 8) * STG_STRIDE + c0]     = v2;
                        stage[(r0 + 8) * STG_STRIDE + c0 + 1] = v3;
                    }
                }
            }
            __syncthreads();
            const int colg = n0 + pair * 64 + lane;
            float* op = out + 1 + (size_t)(m0 + wid * 16) * N_ITEMS;
            #pragma unroll
            for (int r = 0; r < 16; r++) {
                float* rp = op + (size_t)r * N_ITEMS;
                float s0 = stage[(wid * 16 + r) * STG_STRIDE + lane];
                float s1 = stage[(wid * 16 + r) * STG_STRIDE + lane + 32];
                if (colg < N_ITEMS)      rp[colg]      = s0;
                if (colg + 32 < N_ITEMS) rp[colg + 32] = s1;
            }
            if (pair == 0) __syncthreads();
        }
    }

    // reduce squares into loss (pad cols contribute exactly 0)
    #pragma unroll
    for (int o = 16; o > 0; o >>= 1) sq += __shfl_xor_sync(0xFFFFFFFFu, sq, o);
    if (lane == 0) atomicAdd(out, sq);
}

// ---------------- positives: + (1 - 2*s) per unique (row, item) ----------------
__global__ void k_pos(const float* __restrict__ user_emb, const float* __restrict__ item_emb,
                      const int* __restrict__ uid, const int* __restrict__ seq,
                      float* __restrict__ out) {
    const int b = blockIdx.x, t = threadIdx.x;   // 64 threads
    __shared__ int   s_seq[HIST];
    __shared__ float s_red[2];
    if (t < HIST) s_seq[t] = seq[b * HIST + t];
    const float su = user_emb[(size_t)uid[b] * IN_CH + t];
    __syncthreads();
    float contrib = 0.0f;
    for (int j = 0; j < HIST; j++) {
        int idx = s_seq[j];
        bool dup = false;
        for (int jj = 0; jj < j; jj++) dup |= (s_seq[jj] == idx);
        if (!dup) {
            float p = su * item_emb[(size_t)idx * IN_CH + t];
            #pragma unroll
            for (int o = 16; o > 0; o >>= 1) p += __shfl_xor_sync(0xFFFFFFFFu, p, o);
            if ((t & 31) == 0) s_red[t >> 5] = p;
            __syncthreads();
            if (t == 0) contrib += 1.0f - 2.0f * (s_red[0] + s_red[1]);
            __syncthreads();
        }
    }
    if (t == 0) atomicAdd(out, contrib);
}

// ---------------- launch ----------------
extern "C" void kernel_launch(void* const* d_in, const int* in_sizes, int n_in,
                              void* d_out, int out_size) {
    const float* user_emb = (const float*)d_in[0];
    const float* item_emb = (const float*)d_in[1];
    const int*   uid      = (const int*)d_in[2];
    const int*   seq      = (const int*)d_in[3];
    float*       out      = (float*)d_out;   // [0]=loss, [1..]=pref row-major

    cudaFuncSetAttribute(k_gemm, cudaFuncAttributeMaxDynamicSharedMemorySize, SMEM_TOTAL);

    k_init<<<1, 32>>>(out);
    k_prepA<<<(BATCH * 16) / 256, 256>>>(user_emb, uid);
    k_prepB<<<(NPAD * 16) / 256, 256>>>(item_emb);
    k_gemm<<<N_CTAS, 256, SMEM_TOTAL>>>(out);
    k_pos<<<BATCH, 64>>>(user_emb, item_emb, uid, seq, out);
}